// round 3
// baseline (speedup 1.0000x reference)
#include <cuda_runtime.h>
#include <cuda_bf16.h>
#include <cstdint>

#define N_CELLS 600
#define HW      4096
#define NBF     100
#define NPAIR   50
#define MC      20
#define EDGES   21
#define NB      500
#define NB_INIT 100
#define BATCH   32
#define NSTEPS  400
#define CPC     4
#define NCTA    150
#define ROW     (N_CELLS*BATCH)   /* 19200 */

// ---------------- scratch: __device__ globals (no allocations allowed) ----------------
__device__ float g_spk [NB     * N_CELLS * BATCH];  // [t][c][b], canary -1 until written
__device__ float g_gens[NSTEPS * N_CELLS * BATCH];  // [t'][c][b]
__device__ float g_stimT[HW * BATCH];               // [hw][b]
__device__ float g_sapp [N_CELLS * BATCH];          // [c][b]

// ---------------- helpers ----------------
__device__ __forceinline__ float ldg_relaxed(const float* p) {
    float v;
    asm volatile("ld.relaxed.gpu.global.f32 %0, [%1];" : "=f"(v) : "l"(p));
    return v;
}
__device__ __forceinline__ void stg_relaxed(float* p, float v) {
    asm volatile("st.relaxed.gpu.global.f32 [%0], %1;" :: "l"(p), "f"(v) : "memory");
}
__device__ __forceinline__ unsigned long long pk2(float lo, float hi) {
    unsigned long long u;
    asm("mov.b64 %0, {%1, %2};" : "=l"(u) : "f"(lo), "f"(hi));
    return u;
}
__device__ __forceinline__ float lo2(unsigned long long u) {
    float a, b;
    asm("mov.b64 {%0, %1}, %2;" : "=f"(a), "=f"(b) : "l"(u));
    return a;
}
__device__ __forceinline__ float hi2(unsigned long long u) {
    float a, b;
    asm("mov.b64 {%0, %1}, %2;" : "=f"(a), "=f"(b) : "l"(u));
    return b;
}
__device__ __forceinline__ void fma2(unsigned long long& acc, unsigned long long w, unsigned long long s) {
    asm("fma.rn.f32x2 %0, %1, %2, %0;" : "+l"(acc) : "l"(w), "l"(s));
}

// ---------------- setup: transpose stimulus to [hw][b] ----------------
__global__ void k_stimT(const float* __restrict__ stim) {
    int b = blockIdx.x;
    for (int i = threadIdx.x; i < HW; i += blockDim.x)
        g_stimT[i*BATCH + b] = stim[(size_t)b*HW + i];
}

// ---------------- setup: stim_applied[c][b] = stim_flat[b] . spat_flat[c] ----------------
__global__ void k_sapp(const float* __restrict__ spat) {
    __shared__ float red[128];
    int c = blockIdx.x;
    int tid = threadIdx.x;
    int g = tid >> 5, b = tid & 31;           // 4 residue groups x 32 batches
    float acc = 0.f;
    const float* sp = spat + (size_t)c*HW;
    #pragma unroll 8
    for (int m = 0; m < HW/4; m++) {
        int i = g + 4*m;
        acc += sp[i] * g_stimT[i*BATCH + b];
    }
    red[tid] = acc;
    __syncthreads();
    if (tid < 32)
        g_sapp[c*BATCH + tid] = red[tid] + red[tid+32] + red[tid+64] + red[tid+96];
}

// ---------------- setup: initial spikes transposed + canary fill ----------------
__global__ void k_init(const float* __restrict__ init) {
    int idx = blockIdx.x*blockDim.x + threadIdx.x;
    if (idx >= NB*ROW) return;
    int tau = idx / ROW, r = idx % ROW;
    int cc = r / BATCH, b = r % BATCH;
    g_spk[idx] = (tau < NB_INIT) ? init[((size_t)b*N_CELLS + cc)*NB_INIT + tau] : -1.0f;
}

// ---------------- the simulation: 150 CTAs x 128 threads, 1 warp per cell ----------------
__global__ void __launch_bounds__(128, 1)
k_sim(const float* __restrict__ stime,      // (500)
      const float* __restrict__ tcf,        // (600,100)
      const float* __restrict__ fbf,        // (600,100)
      const float* __restrict__ cpf,        // (600,20,100)
      const float* __restrict__ bias,       // (600,1)
      const int*   __restrict__ sel)        // (600,20)
{
    __shared__ float sh_w[CPC][EDGES][NBF];   // tap-reversed filters
    __shared__ float sh_stv[CPC][NSTEPS];     // stim time conv per cell
    __shared__ int   sh_src[CPC][EDGES];
    __shared__ float sh_st[NB];
    __shared__ float sh_tc[CPC][NBF];

    const int tid = threadIdx.x;
    const int c0 = blockIdx.x * CPC;

    for (int i = tid; i < NB; i += 128) sh_st[i] = stime[i];
    for (int i = tid; i < CPC*NBF; i += 128)
        sh_tc[i/NBF][i%NBF] = tcf[(size_t)(c0 + i/NBF)*NBF + (i%NBF)];
    for (int i = tid; i < CPC*EDGES*NBF; i += 128) {
        int lc = i / (EDGES*NBF), r = i % (EDGES*NBF);
        int e = r / NBF, j = r % NBF;
        int c = c0 + lc;
        float v = (e == 0) ? fbf[(size_t)c*NBF + (NBF-1-j)]
                           : cpf[((size_t)c*MC + (e-1))*NBF + (NBF-1-j)];
        sh_w[lc][e][j] = v;
    }
    for (int i = tid; i < CPC*EDGES; i += 128) {
        int lc = i / EDGES, e = i % EDGES;
        sh_src[lc][e] = (e == 0) ? (c0 + lc) : sel[(c0+lc)*MC + (e-1)];
    }
    __syncthreads();
    // stim time conv: stv[lc][t] = sum_f stime[t+f] * tc[lc][f]
    for (int i = tid; i < CPC*NSTEPS; i += 128) {
        int lc = i / NSTEPS, t = i % NSTEPS;
        float s = 0.f;
        #pragma unroll 4
        for (int f = 0; f < NBF; f++) s += sh_st[t+f] * sh_tc[lc][f];
        sh_stv[lc][t] = s;
    }
    __syncthreads();

    const int w = tid >> 5, lane = tid & 31;
    const int c = c0 + w;
    const float sapp = g_sapp[c*BATCH + lane];
    const float bv = bias[c];
    const int myoff = c*BATCH + lane;

    int off[EDGES];
    #pragma unroll
    for (int e = 0; e < EDGES; e++) off[e] = sh_src[w][e]*BATCH + lane;

    // acc ring: pair p holds gensig partials for ring slots 2p (lo), 2p+1 (hi)
    unsigned long long accp[NPAIR];
    #pragma unroll
    for (int p = 0; p < NPAIR; p++) accp[p] = 0ull;

    #pragma unroll 1
    for (int tau = 0; tau < NB; tau++) {
        float s_own;
        if (tau >= NB_INIT) {
            // ring covers steps [tau-100, tau-1]; head = step t = tau-100 (complete)
            int t = tau - NB_INIT;
            float gv = lo2(accp[0]) + sapp * sh_stv[w][t] + bv;
            float s = 1.0f / (1.0f + expf(-gv));
            g_gens[(size_t)t*ROW + myoff] = gv;
            stg_relaxed(&g_spk[(size_t)tau*ROW + myoff], s);
            s_own = s;
        } else {
            s_own = g_spk[(size_t)tau*ROW + myoff];   // prewritten by k_init
        }

        // shift ring by one tap: new acc[j] = old acc[j+1]
        #pragma unroll
        for (int p = 0; p < NPAIR-1; p++) accp[p] = pk2(hi2(accp[p]), lo2(accp[p+1]));
        accp[NPAIR-1] = pk2(hi2(accp[NPAIR-1]), 0.0f);

        // gather the 21 source spikes at time tau (own already in register)
        float sv[EDGES];
        sv[0] = s_own;
        const float* row = g_spk + (size_t)tau*ROW;
        #pragma unroll
        for (int e = 1; e < EDGES; e++) sv[e] = ldg_relaxed(row + off[e]);
        #pragma unroll
        for (int e = 1; e < EDGES; e++) {
            int guard = 0;
            while (__any_sync(0xffffffffu, sv[e] == -1.0f)) {
                sv[e] = ldg_relaxed(row + off[e]);
                if (++guard > (1 << 22)) break;   // backstop: degrade, never hang
            }
        }

        // scatter: acc[j] += w_rev[j] * s  (ring now covers [tau-99, tau]; tap f = 99-j)
        #pragma unroll
        for (int e = 0; e < EDGES; e++) {
            unsigned long long ss = pk2(sv[e], sv[e]);
            const float2* wp = (const float2*)(&sh_w[w][e][0]);
            #pragma unroll
            for (int p = 0; p < NPAIR; p++) {
                float2 wv = wp[p];
                fma2(accp[p], pk2(wv.x, wv.y), ss);
            }
        }
    }
}

// ---------------- output assembly: transpose [t][c][b] -> [b][c][t] ----------------
__global__ void k_out(const float* __restrict__ init, float* __restrict__ out) {
    __shared__ float tile[128][33];
    int c = blockIdx.x, tid = threadIdx.x;
    float* out_s = out;                                      // (32,600,500)
    float* out_g = out + (size_t)BATCH*N_CELLS*NB;           // (32,600,400)

    // initial spikes: same layout as output, straight copy
    for (int i = tid; i < BATCH*NB_INIT; i += 128) {
        int b = i / NB_INIT, t = i % NB_INIT;
        out_s[(size_t)b*(N_CELLS*NB) + (size_t)c*NB + t] =
            init[((size_t)b*N_CELLS + c)*NB_INIT + t];
    }
    // simulated spikes, t in [100,500)
    for (int t0 = NB_INIT; t0 < NB; t0 += 128) {
        int chunk = min(128, NB - t0);
        __syncthreads();
        for (int i = tid; i < chunk*BATCH; i += 128) {
            int tl = i / BATCH, b = i % BATCH;
            tile[tl][b] = g_spk[(size_t)(t0+tl)*ROW + c*BATCH + b];
        }
        __syncthreads();
        for (int i = tid; i < chunk*BATCH; i += 128) {
            int b = i / chunk, tl = i % chunk;
            out_s[(size_t)b*(N_CELLS*NB) + (size_t)c*NB + (t0+tl)] = tile[tl][b];
        }
    }
    // generator signal, t' in [0,400)
    for (int t0 = 0; t0 < NSTEPS; t0 += 128) {
        int chunk = min(128, NSTEPS - t0);
        __syncthreads();
        for (int i = tid; i < chunk*BATCH; i += 128) {
            int tl = i / BATCH, b = i % BATCH;
            tile[tl][b] = g_gens[(size_t)(t0+tl)*ROW + c*BATCH + b];
        }
        __syncthreads();
        for (int i = tid; i < chunk*BATCH; i += 128) {
            int b = i / chunk, tl = i % chunk;
            out_g[(size_t)b*(N_CELLS*NSTEPS) + (size_t)c*NSTEPS + (t0+tl)] = tile[tl][b];
        }
    }
}

// ---------------- launch ----------------
extern "C" void kernel_launch(void* const* d_in, const int* in_sizes, int n_in,
                              void* d_out, int out_size) {
    const float* stim  = (const float*)d_in[0];   // (32,64,64)
    const float* init  = (const float*)d_in[1];   // (32,600,100)
    const float* spat  = (const float*)d_in[2];   // (600,64,64)
    const float* tcf   = (const float*)d_in[3];   // (600,100)
    const float* fbf   = (const float*)d_in[4];   // (600,100)
    const float* cpf   = (const float*)d_in[5];   // (600,20,100)
    const float* bias  = (const float*)d_in[6];   // (600,1)
    const int*   sel   = (const int*)d_in[7];     // (600,20)
    const float* stime = (const float*)d_in[8];   // (500,)
    float* out = (float*)d_out;

    k_stimT<<<BATCH, 256>>>(stim);
    k_sapp<<<N_CELLS, 128>>>(spat);
    k_init<<<(NB*ROW + 255)/256, 256>>>(init);
    k_sim<<<NCTA, 128>>>(stime, tcf, fbf, cpf, bias, sel);
    k_out<<<N_CELLS, 128>>>(init, out);
}

// round 4
// speedup vs baseline: 1.1346x; 1.1346x over previous
#include <cuda_runtime.h>
#include <cuda_bf16.h>
#include <cstdint>

#define N_CELLS 600
#define HW      4096
#define NBF     100
#define MC      20
#define EDGES   21
#define NB      500
#define NB_INIT 100
#define BATCH   32
#define NSTEPS  400
#define ROW     (N_CELLS*BATCH)   /* 19200 */

// ring split: 3 warps per cell, 36 slots each (108 total, slots >=100 are zero-weight pad)
#define WPC     3
#define SLOTS   36
#define NPW     18                 /* pairs per warp */
#define NQ      9                  /* float4 loads per edge per warp */
#define RING    108
#define CPC     2                  /* cells per CTA */
#define TPB     (CPC*WPC*32)       /* 192 threads */
#define NCTA    (N_CELLS/CPC)      /* 300 CTAs */

// ---------------- scratch: __device__ globals (no allocations allowed) ----------------
__device__ float g_spk [NB     * N_CELLS * BATCH];  // [t][c][b], canary -1 until written
__device__ float g_gens[NSTEPS * N_CELLS * BATCH];  // [t'][c][b]
__device__ float g_stimT[HW * BATCH];               // [hw][b]
__device__ float g_sapp [N_CELLS * BATCH];          // [c][b]

// ---------------- helpers ----------------
__device__ __forceinline__ float ldg_relaxed(const float* p) {
    float v;
    asm volatile("ld.relaxed.gpu.global.f32 %0, [%1];" : "=f"(v) : "l"(p));
    return v;
}
__device__ __forceinline__ void stg_relaxed(float* p, float v) {
    asm volatile("st.relaxed.gpu.global.f32 [%0], %1;" :: "l"(p), "f"(v) : "memory");
}
__device__ __forceinline__ unsigned long long pk2(float lo, float hi) {
    unsigned long long u;
    asm("mov.b64 %0, {%1, %2};" : "=l"(u) : "f"(lo), "f"(hi));
    return u;
}
__device__ __forceinline__ float lo2(unsigned long long u) {
    float a, b;
    asm("mov.b64 {%0, %1}, %2;" : "=f"(a), "=f"(b) : "l"(u));
    return a;
}
__device__ __forceinline__ float hi2(unsigned long long u) {
    float a, b;
    asm("mov.b64 {%0, %1}, %2;" : "=f"(a), "=f"(b) : "l"(u));
    return b;
}
__device__ __forceinline__ void fma2(unsigned long long& acc, unsigned long long w, unsigned long long s) {
    asm("fma.rn.f32x2 %0, %1, %2, %0;" : "+l"(acc) : "l"(w), "l"(s));
}

// ---------------- setup: transpose stimulus to [hw][b] ----------------
__global__ void k_stimT(const float* __restrict__ stim) {
    int b = blockIdx.x;
    for (int i = threadIdx.x; i < HW; i += blockDim.x)
        g_stimT[i*BATCH + b] = stim[(size_t)b*HW + i];
}

// ---------------- setup: stim_applied[c][b] = stim_flat[b] . spat_flat[c] ----------------
__global__ void k_sapp(const float* __restrict__ spat) {
    __shared__ float red[128];
    int c = blockIdx.x;
    int tid = threadIdx.x;
    int g = tid >> 5, b = tid & 31;
    float acc = 0.f;
    const float* sp = spat + (size_t)c*HW;
    #pragma unroll 8
    for (int m = 0; m < HW/4; m++) {
        int i = g + 4*m;
        acc += sp[i] * g_stimT[i*BATCH + b];
    }
    red[tid] = acc;
    __syncthreads();
    if (tid < 32)
        g_sapp[c*BATCH + tid] = red[tid] + red[tid+32] + red[tid+64] + red[tid+96];
}

// ---------------- setup: initial spikes transposed + canary fill ----------------
__global__ void k_init(const float* __restrict__ init) {
    int idx = blockIdx.x*blockDim.x + threadIdx.x;
    if (idx >= NB*ROW) return;
    int tau = idx / ROW, r = idx % ROW;
    int cc = r / BATCH, b = r % BATCH;
    g_spk[idx] = (tau < NB_INIT) ? init[((size_t)b*N_CELLS + cc)*NB_INIT + tau] : -1.0f;
}

// ---------------- the simulation: 300 CTAs x 192 threads; 3 warps per cell (systolic ring) --
__global__ void __launch_bounds__(TPB, 3)
k_sim(const float* __restrict__ stime,      // (500)
      const float* __restrict__ tcf,        // (600,100)
      const float* __restrict__ fbf,        // (600,100)
      const float* __restrict__ cpf,        // (600,20,100)
      const float* __restrict__ bias,       // (600,1)
      const int*   __restrict__ sel)        // (600,20)
{
    __shared__ __align__(16) float sh_w[CPC][EDGES][RING]; // tap-reversed, zero-padded
    __shared__ float sh_stv[CPC][NSTEPS];
    __shared__ int   sh_srcoff[CPC][EDGES];                // src*BATCH
    __shared__ float sh_st[NB];
    __shared__ float sh_tc[CPC][NBF];
    __shared__ float sh_spk[2][CPC][32];                   // double-buffered own spike
    __shared__ float sh_bnd[2][CPC][WPC][32];              // double-buffered boundary export

    const int tid = threadIdx.x;
    const int c0 = blockIdx.x * CPC;

    for (int i = tid; i < NB; i += TPB) sh_st[i] = stime[i];
    for (int i = tid; i < CPC*NBF; i += TPB)
        sh_tc[i/NBF][i%NBF] = tcf[(size_t)(c0 + i/NBF)*NBF + (i%NBF)];
    for (int i = tid; i < CPC*EDGES*RING; i += TPB) {
        int lc = i / (EDGES*RING), rr = i % (EDGES*RING);
        int e = rr / RING, j = rr % RING;
        int c = c0 + lc;
        float v = 0.0f;
        if (j < NBF)
            v = (e == 0) ? fbf[(size_t)c*NBF + (NBF-1-j)]
                         : cpf[((size_t)c*MC + (e-1))*NBF + (NBF-1-j)];
        sh_w[lc][e][j] = v;
    }
    for (int i = tid; i < CPC*EDGES; i += TPB) {
        int lc = i / EDGES, e = i % EDGES;
        int src = (e == 0) ? (c0 + lc) : sel[(c0+lc)*MC + (e-1)];
        sh_srcoff[lc][e] = src * BATCH;
    }
    __syncthreads();
    for (int i = tid; i < CPC*NSTEPS; i += TPB) {
        int lc = i / NSTEPS, t = i % NSTEPS;
        float s = 0.f;
        #pragma unroll 4
        for (int f = 0; f < NBF; f++) s += sh_st[t+f] * sh_tc[lc][f];
        sh_stv[lc][t] = s;
    }
    __syncthreads();

    const int wid = tid >> 5, lane = tid & 31;
    const int lc = wid / WPC, r = wid % WPC;   // local cell, ring segment
    const int c = c0 + lc;
    const int myoff = c*BATCH + lane;
    const float sapp = g_sapp[myoff];
    const float bv = bias[c];
    const float* wbase = &sh_w[lc][0][0] + r*SLOTS;   // segment start (16B-aligned: 36r)

    unsigned long long accp[NPW];
    #pragma unroll
    for (int p = 0; p < NPW; p++) accp[p] = 0ull;

    #pragma unroll 1
    for (int tau = 0; tau < NB; tau++) {
        const int par = tau & 1;
        float s_own = 0.0f;

        if (r == 0) {
            if (tau >= NB_INIT) {
                int t = tau - NB_INIT;
                float gv = lo2(accp[0]) + sapp * sh_stv[lc][t] + bv;
                float s = 1.0f / (1.0f + expf(-gv));
                g_gens[(size_t)t*ROW + myoff] = gv;
                stg_relaxed(&g_spk[(size_t)tau*ROW + myoff], s);
                s_own = s;
            } else {
                s_own = g_spk[(size_t)tau*ROW + myoff];  // prewritten by k_init
            }
            sh_spk[par][lc][lane] = s_own;
        } else {
            sh_bnd[par][lc][r][lane] = lo2(accp[0]);     // export lowest slot
        }
        __syncthreads();

        // shift ring segment down by one slot
        float incoming = (r < WPC-1) ? sh_bnd[par][lc][r+1][lane] : 0.0f;
        #pragma unroll
        for (int p = 0; p < NPW-1; p++) accp[p] = pk2(hi2(accp[p]), lo2(accp[p+1]));
        accp[NPW-1] = pk2(hi2(accp[NPW-1]), incoming);

        // gather source spikes at time tau
        float sv[EDGES];
        sv[0] = (r == 0) ? s_own : sh_spk[par][lc][lane];
        const float* row = g_spk + (size_t)tau*ROW;
        #pragma unroll
        for (int e = 1; e < EDGES; e++)
            sv[e] = ldg_relaxed(row + sh_srcoff[lc][e] + lane);
        if (tau >= NB_INIT) {
            #pragma unroll
            for (int e = 1; e < EDGES; e++) {
                int guard = 0;
                while (__any_sync(0xffffffffu, sv[e] == -1.0f)) {
                    sv[e] = ldg_relaxed(row + sh_srcoff[lc][e] + lane);
                    if (++guard > (1 << 22)) break;   // backstop: degrade, never hang
                }
            }
        }

        // scatter into this warp's 36 slots, all 21 edges
        #pragma unroll
        for (int e = 0; e < EDGES; e++) {
            unsigned long long ss = pk2(sv[e], sv[e]);
            const float4* wp = (const float4*)(wbase + e*RING);
            #pragma unroll
            for (int q = 0; q < NQ; q++) {
                float4 w4 = wp[q];
                fma2(accp[2*q],   pk2(w4.x, w4.y), ss);
                fma2(accp[2*q+1], pk2(w4.z, w4.w), ss);
            }
        }
    }
}

// ---------------- output assembly: transpose [t][c][b] -> [b][c][t] ----------------
__global__ void k_out(const float* __restrict__ init, float* __restrict__ out) {
    __shared__ float tile[128][33];
    int c = blockIdx.x, tid = threadIdx.x;
    float* out_s = out;                                      // (32,600,500)
    float* out_g = out + (size_t)BATCH*N_CELLS*NB;           // (32,600,400)

    for (int i = tid; i < BATCH*NB_INIT; i += 128) {
        int b = i / NB_INIT, t = i % NB_INIT;
        out_s[(size_t)b*(N_CELLS*NB) + (size_t)c*NB + t] =
            init[((size_t)b*N_CELLS + c)*NB_INIT + t];
    }
    for (int t0 = NB_INIT; t0 < NB; t0 += 128) {
        int chunk = min(128, NB - t0);
        __syncthreads();
        for (int i = tid; i < chunk*BATCH; i += 128) {
            int tl = i / BATCH, b = i % BATCH;
            tile[tl][b] = g_spk[(size_t)(t0+tl)*ROW + c*BATCH + b];
        }
        __syncthreads();
        for (int i = tid; i < chunk*BATCH; i += 128) {
            int b = i / chunk, tl = i % chunk;
            out_s[(size_t)b*(N_CELLS*NB) + (size_t)c*NB + (t0+tl)] = tile[tl][b];
        }
    }
    for (int t0 = 0; t0 < NSTEPS; t0 += 128) {
        int chunk = min(128, NSTEPS - t0);
        __syncthreads();
        for (int i = tid; i < chunk*BATCH; i += 128) {
            int tl = i / BATCH, b = i % BATCH;
            tile[tl][b] = g_gens[(size_t)(t0+tl)*ROW + c*BATCH + b];
        }
        __syncthreads();
        for (int i = tid; i < chunk*BATCH; i += 128) {
            int b = i / chunk, tl = i % chunk;
            out_g[(size_t)b*(N_CELLS*NSTEPS) + (size_t)c*NSTEPS + (t0+tl)] = tile[tl][b];
        }
    }
}

// ---------------- launch ----------------
extern "C" void kernel_launch(void* const* d_in, const int* in_sizes, int n_in,
                              void* d_out, int out_size) {
    const float* stim  = (const float*)d_in[0];   // (32,64,64)
    const float* init  = (const float*)d_in[1];   // (32,600,100)
    const float* spat  = (const float*)d_in[2];   // (600,64,64)
    const float* tcf   = (const float*)d_in[3];   // (600,100)
    const float* fbf   = (const float*)d_in[4];   // (600,100)
    const float* cpf   = (const float*)d_in[5];   // (600,20,100)
    const float* bias  = (const float*)d_in[6];   // (600,1)
    const int*   sel   = (const int*)d_in[7];     // (600,20)
    const float* stime = (const float*)d_in[8];   // (500,)
    float* out = (float*)d_out;

    k_stimT<<<BATCH, 256>>>(stim);
    k_sapp<<<N_CELLS, 128>>>(spat);
    k_init<<<(NB*ROW + 255)/256, 256>>>(init);
    k_sim<<<NCTA, TPB>>>(stime, tcf, fbf, cpf, bias, sel);
    k_out<<<N_CELLS, 128>>>(init, out);
}